// round 15
// baseline (speedup 1.0000x reference)
#include <cuda_runtime.h>
#include <cuda_fp16.h>
#include <cstdint>

#define NN 100000
#define NE 1200000
#define D  64
#define SCAN_B 1024
#define NB ((NN + SCAN_B - 1) / SCAN_B)   // 98

// Scratch (device globals — no allocation allowed; zero-initialized at load)
__device__ float              g_dis[NN];      // rsqrt(degree)
__device__ __half2            g_h[NN * D / 2];
__device__ unsigned long long g_pk64[NN];     // hi: count, lo: fixed-point wdeg
__device__ int                g_off[NN];      // segment start per node
__device__ int                g_cnt[NN];      // segment length per node
__device__ int                g_rank[NE];     // edge rank within dst segment
__device__ int                g_total;        // segment allocator (reset by k_gemm)
__device__ int2               g_pack[NE];     // {src, bits(dis[src]*ew)}

// ---------------------------------------------------------------------------
// one packed 64-bit atomic per edge; the returned old count IS the edge's
// rank within its dst segment -> no second atomic pass needed.
__global__ void k_deg(const int* __restrict__ dst, const float* __restrict__ ew) {
    int e = blockIdx.x * blockDim.x + threadIdx.x;
    if (e < NE) {
        unsigned int q = __float2uint_rn(ew[e] * 16777216.0f);
        unsigned long long inc = (1ULL << 32) | (unsigned long long)q;
        unsigned long long old = atomicAdd(&g_pk64[dst[e]], inc);
        g_rank[e] = (int)(old >> 32);
    }
}

// ---------------------------------------------------------------------------
// Offsets in ONE kernel: block-local scan + one atomicAdd of the block total.
// Segment placement is arbitrary (block completion order) — valid because
// k_aggr reads {off, cnt}. Fuses dis = rsqrt(deg) and the g_pk64 reset.
__global__ __launch_bounds__(SCAN_B) void k_offsets() {
    __shared__ int wsum[32];
    __shared__ int s_base;
    const int i    = blockIdx.x * SCAN_B + threadIdx.x;
    const int lane = threadIdx.x & 31, w = threadIdx.x >> 5;

    unsigned long long p = (i < NN) ? g_pk64[i] : 0ULL;
    if (i < NN) g_pk64[i] = 0ULL;           // clean slate for next replay
    int v = (int)(p >> 32);
    int s = v;
    #pragma unroll
    for (int d = 1; d < 32; d <<= 1) {
        int t = __shfl_up_sync(0xffffffffu, s, d);
        if (lane >= d) s += t;
    }
    if (lane == 31) wsum[w] = s;
    __syncthreads();
    if (w == 0) {
        int t = wsum[lane];
        #pragma unroll
        for (int d = 1; d < 32; d <<= 1) {
            int u = __shfl_up_sync(0xffffffffu, t, d);
            if (lane >= d) t += u;
        }
        wsum[lane] = t;
    }
    __syncthreads();
    const int excl   = s + ((w > 0) ? wsum[w - 1] : 0) - v;  // block-local excl
    const int btotal = wsum[31];
    if (threadIdx.x == 0) s_base = atomicAdd(&g_total, btotal);
    __syncthreads();

    if (i < NN) {
        g_off[i] = s_base + excl;
        g_cnt[i] = v;
        float deg = 1.0f + (float)(unsigned int)p * (1.0f / 16777216.0f);
        g_dis[i] = rsqrtf(deg);
    }
}

// ---------------------------------------------------------------------------
// Fill CSR: pos = off[dst] + rank (precomputed) — NO atomic round-trip.
__global__ void k_fill(const int* __restrict__ src, const int* __restrict__ dst,
                       const float* __restrict__ ew) {
    int e = blockIdx.x * blockDim.x + threadIdx.x;
    if (e >= NE) return;
    int s = src[e], d = dst[e];
    int pos = g_off[d] + g_rank[e];
    float m = g_dis[s] * ew[e];
    g_pack[pos] = make_int2(s, __float_as_int(m));
}

// ---------------------------------------------------------------------------
// HMMA GEMM, A direct-from-global: h = x @ W^T (fp16 in, f32 accum) -> g_h.
// B fragments loaded from smem per k-chunk (kc loop NOT unrolled) to keep
// register count low -> higher occupancy. Also resets g_total.
#define GROWS 128
#define XST 72
__global__ __launch_bounds__(256) void k_gemm(const float* __restrict__ x,
                                              const float* __restrict__ W) {
    if (blockIdx.x == 0 && threadIdx.x == 0) g_total = 0;

    __shared__ __half Ws[D * XST];

    const int tid  = threadIdx.x;
    const int lane = tid & 31;
    const int wid  = tid >> 5;
    const int base = blockIdx.x * GROWS;

    for (int t = tid; t < D * D; t += 256) {
        int j = t >> 6, k = t & 63;
        Ws[j * XST + k] = __float2half_rn(W[t]);
    }
    __syncthreads();

    float acc[8][4];
    #pragma unroll
    for (int nb = 0; nb < 8; nb++)
        #pragma unroll
        for (int j = 0; j < 4; j++) acc[nb][j] = 0.f;

    const int gid = lane >> 2, tig = lane & 3;
    const int bn  = lane >> 2;            // B frag row within nb block
    const int bk0 = (lane & 3) << 1;      // B frag k offset
    const int r0  = base + wid * 16 + gid;
    const int r1  = r0 + 8;
    const bool v0 = r0 < NN, v1 = r1 < NN;
    const float* xr0 = &x[(size_t)(v0 ? r0 : 0) * D + 2 * tig];
    const float* xr1 = &x[(size_t)(v1 ? r1 : 0) * D + 2 * tig];

    #pragma unroll 1
    for (int kc = 0; kc < 4; kc++) {
        float2 z = make_float2(0.f, 0.f);
        float2 f00 = v0 ? *(const float2*)&xr0[16 * kc]     : z;
        float2 f10 = v1 ? *(const float2*)&xr1[16 * kc]     : z;
        float2 f01 = v0 ? *(const float2*)&xr0[16 * kc + 8] : z;
        float2 f11 = v1 ? *(const float2*)&xr1[16 * kc + 8] : z;
        __half2 ha0 = __floats2half2_rn(f00.x, f00.y);
        __half2 ha1 = __floats2half2_rn(f10.x, f10.y);
        __half2 ha2 = __floats2half2_rn(f01.x, f01.y);
        __half2 ha3 = __floats2half2_rn(f11.x, f11.y);
        uint32_t a0 = *(uint32_t*)&ha0, a1 = *(uint32_t*)&ha1;
        uint32_t a2 = *(uint32_t*)&ha2, a3 = *(uint32_t*)&ha3;

        uint32_t bf[8][2];
        #pragma unroll
        for (int nb = 0; nb < 8; nb++) {
            const __half* wp = &Ws[(nb * 8 + bn) * XST + kc * 16];
            bf[nb][0] = *(const uint32_t*)&wp[bk0];
            bf[nb][1] = *(const uint32_t*)&wp[bk0 + 8];
        }
        #pragma unroll
        for (int nb = 0; nb < 8; nb++) {
            asm volatile(
                "mma.sync.aligned.m16n8k16.row.col.f32.f16.f16.f32 "
                "{%0,%1,%2,%3}, {%4,%5,%6,%7}, {%8,%9}, {%0,%1,%2,%3};"
                : "+f"(acc[nb][0]), "+f"(acc[nb][1]),
                  "+f"(acc[nb][2]), "+f"(acc[nb][3])
                : "r"(a0), "r"(a1), "r"(a2), "r"(a3),
                  "r"(bf[nb][0]), "r"(bf[nb][1]));
        }
    }

    const int cc = tig << 1;
    #pragma unroll
    for (int nb = 0; nb < 8; nb++) {
        int c0 = nb * 8 + cc;
        if (v0) g_h[(r0 * D + c0) >> 1] = __floats2half2_rn(acc[nb][0], acc[nb][1]);
        if (v1) g_h[(r1 * D + c0) >> 1] = __floats2half2_rn(acc[nb][2], acc[nb][3]);
    }
}

// ---------------------------------------------------------------------------
// Aggregate (gather form): warp per dst node, unroll x4 for MLP.
// out[d] = relu( dis[d] * ( dis[d]*h[d] + sum_e m_e*h[src_e] ) + b )
__global__ __launch_bounds__(256) void k_aggr(const float* __restrict__ b,
                                              float* __restrict__ out) {
    int gw   = (blockIdx.x * 256 + threadIdx.x) >> 5;
    int lane = threadIdx.x & 31;
    if (gw >= NN) return;

    int off = g_off[gw];
    int end = off + g_cnt[gw];
    float dd = g_dis[gw];

    float2 hd = __half22float2(g_h[gw * (D / 2) + lane]);
    float2 acc = make_float2(dd * hd.x, dd * hd.y);

    for (int eb = off; eb < end; eb += 32) {
        int n = min(32, end - eb);
        int2 pk = make_int2(0, 0);
        if (lane < n) pk = g_pack[eb + lane];
        int j = 0;
        for (; j + 4 <= n; j += 4) {
            int   s0 = __shfl_sync(0xffffffffu, pk.x, j);
            int   s1 = __shfl_sync(0xffffffffu, pk.x, j + 1);
            int   s2 = __shfl_sync(0xffffffffu, pk.x, j + 2);
            int   s3 = __shfl_sync(0xffffffffu, pk.x, j + 3);
            float m0 = __int_as_float(__shfl_sync(0xffffffffu, pk.y, j));
            float m1 = __int_as_float(__shfl_sync(0xffffffffu, pk.y, j + 1));
            float m2 = __int_as_float(__shfl_sync(0xffffffffu, pk.y, j + 2));
            float m3 = __int_as_float(__shfl_sync(0xffffffffu, pk.y, j + 3));
            float2 f0 = __half22float2(g_h[s0 * (D / 2) + lane]);
            float2 f1 = __half22float2(g_h[s1 * (D / 2) + lane]);
            float2 f2 = __half22float2(g_h[s2 * (D / 2) + lane]);
            float2 f3 = __half22float2(g_h[s3 * (D / 2) + lane]);
            acc.x = fmaf(m0, f0.x, acc.x); acc.y = fmaf(m0, f0.y, acc.y);
            acc.x = fmaf(m1, f1.x, acc.x); acc.y = fmaf(m1, f1.y, acc.y);
            acc.x = fmaf(m2, f2.x, acc.x); acc.y = fmaf(m2, f2.y, acc.y);
            acc.x = fmaf(m3, f3.x, acc.x); acc.y = fmaf(m3, f3.y, acc.y);
        }
        for (; j < n; j++) {
            int   sj = __shfl_sync(0xffffffffu, pk.x, j);
            float mj = __int_as_float(__shfl_sync(0xffffffffu, pk.y, j));
            float2 f = __half22float2(g_h[sj * (D / 2) + lane]);
            acc.x = fmaf(mj, f.x, acc.x);
            acc.y = fmaf(mj, f.y, acc.y);
        }
    }

    float2 bb = *(const float2*)&b[2 * lane];
    float2 o;
    o.x = fmaxf(fmaf(dd, acc.x, bb.x), 0.f);
    o.y = fmaxf(fmaf(dd, acc.y, bb.y), 0.f);
    *(float2*)&out[gw * D + 2 * lane] = o;
}

// ---------------------------------------------------------------------------
extern "C" void kernel_launch(void* const* d_in, const int* in_sizes, int n_in,
                              void* d_out, int out_size) {
    const float* x  = (const float*)d_in[0];
    const int*   ei = (const int*)d_in[1];     // [2, NE] row-major
    const float* ea = (const float*)d_in[2];
    const float* W  = (const float*)d_in[3];
    const float* b  = (const float*)d_in[4];
    float* out = (float*)d_out;

    const int* src = ei;
    const int* dst = ei + NE;

    k_deg<<<(NE + 255) / 256, 256>>>(dst, ea);   // + rank capture
    k_offsets<<<NB, SCAN_B>>>();                 // scan + rsqrt + pk64 reset
    k_fill<<<(NE + 255) / 256, 256>>>(src, dst, ea);
    k_gemm<<<(NN + GROWS - 1) / GROWS, 256>>>(x, W);   // + g_total reset
    k_aggr<<<(NN * 32 + 255) / 256, 256>>>(b, out);
}

// round 16
// speedup vs baseline: 1.0736x; 1.0736x over previous
#include <cuda_runtime.h>
#include <cuda_fp16.h>
#include <cstdint>

#define NN 100000
#define NE 1200000
#define D  64
#define SCAN_B 1024
#define NB ((NN + SCAN_B - 1) / SCAN_B)   // 98

// Scratch (device globals — no allocation allowed; zero-initialized at load)
__device__ float              g_dis[NN];      // rsqrt(degree)
__device__ __half2            g_h[NN * D / 2];
__device__ unsigned long long g_pk64[NN];     // hi: count, lo: fixed-point wdeg
__device__ int                g_off[NN];      // segment start per node
__device__ int                g_cnt[NN];      // segment length per node
__device__ int                g_cur[NN];      // fill cursors
__device__ int                g_total;        // segment allocator (reset by k_gemm)
__device__ int2               g_pack[NE];     // {src, bits(dis[src]*ew)}

// ---------------------------------------------------------------------------
// one packed 64-bit atomic per edge: count + fixed-point weighted degree
// (return value unused -> compiles to fire-and-forget RED)
__global__ void k_deg(const int* __restrict__ dst, const float* __restrict__ ew) {
    int e = blockIdx.x * blockDim.x + threadIdx.x;
    if (e < NE) {
        unsigned int q = __float2uint_rn(ew[e] * 16777216.0f);
        unsigned long long inc = (1ULL << 32) | (unsigned long long)q;
        atomicAdd(&g_pk64[dst[e]], inc);
    }
}

// ---------------------------------------------------------------------------
// Offsets in ONE kernel: block-local scan + one atomicAdd of the block total.
// Segment placement is arbitrary (block completion order) — valid because
// k_aggr reads {off, cnt}. Fuses dis = rsqrt(deg) and the g_pk64 reset.
__global__ __launch_bounds__(SCAN_B) void k_offsets() {
    __shared__ int wsum[32];
    __shared__ int s_base;
    const int i    = blockIdx.x * SCAN_B + threadIdx.x;
    const int lane = threadIdx.x & 31, w = threadIdx.x >> 5;

    unsigned long long p = (i < NN) ? g_pk64[i] : 0ULL;
    if (i < NN) g_pk64[i] = 0ULL;           // clean slate for next replay
    int v = (int)(p >> 32);
    int s = v;
    #pragma unroll
    for (int d = 1; d < 32; d <<= 1) {
        int t = __shfl_up_sync(0xffffffffu, s, d);
        if (lane >= d) s += t;
    }
    if (lane == 31) wsum[w] = s;
    __syncthreads();
    if (w == 0) {
        int t = wsum[lane];
        #pragma unroll
        for (int d = 1; d < 32; d <<= 1) {
            int u = __shfl_up_sync(0xffffffffu, t, d);
            if (lane >= d) t += u;
        }
        wsum[lane] = t;
    }
    __syncthreads();
    const int excl   = s + ((w > 0) ? wsum[w - 1] : 0) - v;  // block-local excl
    const int btotal = wsum[31];
    if (threadIdx.x == 0) s_base = atomicAdd(&g_total, btotal);
    __syncthreads();

    if (i < NN) {
        int o = s_base + excl;
        g_off[i] = o;
        g_cur[i] = o;
        g_cnt[i] = v;
        float deg = 1.0f + (float)(unsigned int)p * (1.0f / 16777216.0f);
        g_dis[i] = rsqrtf(deg);
    }
}

// ---------------------------------------------------------------------------
// Fill CSR: pack {src, dis[src]*ew} (norm computed HERE — k_aggr stays lean).
__global__ void k_fill(const int* __restrict__ src, const int* __restrict__ dst,
                       const float* __restrict__ ew) {
    int e = blockIdx.x * blockDim.x + threadIdx.x;
    if (e >= NE) return;
    int s = src[e], d = dst[e];
    int pos = atomicAdd(&g_cur[d], 1);
    float m = g_dis[s] * ew[e];
    g_pack[pos] = make_int2(s, __float_as_int(m));
}

// ---------------------------------------------------------------------------
// HMMA GEMM, A direct-from-global: h = x @ W^T (fp16 in, f32 accum) -> g_h.
// ALL 16 x-loads prefetched (MLP=16); B fragments re-read from smem per
// k-chunk to keep registers moderate. Also resets g_total.
#define GROWS 128
#define XST 72
__global__ __launch_bounds__(256) void k_gemm(const float* __restrict__ x,
                                              const float* __restrict__ W) {
    if (blockIdx.x == 0 && threadIdx.x == 0) g_total = 0;

    __shared__ __half Ws[D * XST];

    const int tid  = threadIdx.x;
    const int lane = tid & 31;
    const int wid  = tid >> 5;
    const int base = blockIdx.x * GROWS;

    for (int t = tid; t < D * D; t += 256) {
        int j = t >> 6, k = t & 63;
        Ws[j * XST + k] = __float2half_rn(W[t]);
    }
    __syncthreads();

    float acc[8][4];
    #pragma unroll
    for (int nb = 0; nb < 8; nb++)
        #pragma unroll
        for (int j = 0; j < 4; j++) acc[nb][j] = 0.f;

    const int gid = lane >> 2, tig = lane & 3;
    const int bn  = lane >> 2;            // B frag row within nb block
    const int bk0 = (lane & 3) << 1;      // B frag k offset
    const int r0  = base + wid * 16 + gid;
    const int r1  = r0 + 8;
    const bool v0 = r0 < NN, v1 = r1 < NN;
    const float* xr0 = &x[(size_t)(v0 ? r0 : 0) * D + 2 * tig];
    const float* xr1 = &x[(size_t)(v1 ? r1 : 0) * D + 2 * tig];

    // Prefetch ALL A-data: 16 independent 8B loads in flight.
    float2 f0v[8], f1v[8];                 // [kc*2 + half]
    {
        float2 z = make_float2(0.f, 0.f);
        #pragma unroll
        for (int kc = 0; kc < 4; kc++) {
            f0v[2 * kc]     = v0 ? *(const float2*)&xr0[16 * kc]     : z;
            f0v[2 * kc + 1] = v0 ? *(const float2*)&xr0[16 * kc + 8] : z;
            f1v[2 * kc]     = v1 ? *(const float2*)&xr1[16 * kc]     : z;
            f1v[2 * kc + 1] = v1 ? *(const float2*)&xr1[16 * kc + 8] : z;
        }
    }

    #pragma unroll
    for (int kc = 0; kc < 4; kc++) {
        __half2 ha0 = __floats2half2_rn(f0v[2 * kc].x,     f0v[2 * kc].y);
        __half2 ha1 = __floats2half2_rn(f1v[2 * kc].x,     f1v[2 * kc].y);
        __half2 ha2 = __floats2half2_rn(f0v[2 * kc + 1].x, f0v[2 * kc + 1].y);
        __half2 ha3 = __floats2half2_rn(f1v[2 * kc + 1].x, f1v[2 * kc + 1].y);
        uint32_t a0 = *(uint32_t*)&ha0, a1 = *(uint32_t*)&ha1;
        uint32_t a2 = *(uint32_t*)&ha2, a3 = *(uint32_t*)&ha3;

        #pragma unroll
        for (int nb = 0; nb < 8; nb++) {
            const __half* wp = &Ws[(nb * 8 + bn) * XST + kc * 16];
            uint32_t b0 = *(const uint32_t*)&wp[bk0];
            uint32_t b1 = *(const uint32_t*)&wp[bk0 + 8];
            asm volatile(
                "mma.sync.aligned.m16n8k16.row.col.f32.f16.f16.f32 "
                "{%0,%1,%2,%3}, {%4,%5,%6,%7}, {%8,%9}, {%0,%1,%2,%3};"
                : "+f"(acc[nb][0]), "+f"(acc[nb][1]),
                  "+f"(acc[nb][2]), "+f"(acc[nb][3])
                : "r"(a0), "r"(a1), "r"(a2), "r"(a3),
                  "r"(b0), "r"(b1));
        }
    }

    const int cc = tig << 1;
    #pragma unroll
    for (int nb = 0; nb < 8; nb++) {
        int c0 = nb * 8 + cc;
        if (v0) g_h[(r0 * D + c0) >> 1] = __floats2half2_rn(acc[nb][0], acc[nb][1]);
        if (v1) g_h[(r1 * D + c0) >> 1] = __floats2half2_rn(acc[nb][2], acc[nb][3]);
    }
}

// ---------------------------------------------------------------------------
// Aggregate (gather form): warp per dst node, unroll x4 for MLP.
// out[d] = relu( dis[d] * ( dis[d]*h[d] + sum_e m_e*h[src_e] ) + b )
__global__ __launch_bounds__(256) void k_aggr(const float* __restrict__ b,
                                              float* __restrict__ out) {
    int gw   = (blockIdx.x * 256 + threadIdx.x) >> 5;
    int lane = threadIdx.x & 31;
    if (gw >= NN) return;

    int off = g_off[gw];
    int end = off + g_cnt[gw];
    float dd = g_dis[gw];

    float2 hd = __half22float2(g_h[gw * (D / 2) + lane]);
    float2 acc = make_float2(dd * hd.x, dd * hd.y);

    for (int eb = off; eb < end; eb += 32) {
        int n = min(32, end - eb);
        int2 pk = make_int2(0, 0);
        if (lane < n) pk = g_pack[eb + lane];
        int j = 0;
        for (; j + 4 <= n; j += 4) {
            int   s0 = __shfl_sync(0xffffffffu, pk.x, j);
            int   s1 = __shfl_sync(0xffffffffu, pk.x, j + 1);
            int   s2 = __shfl_sync(0xffffffffu, pk.x, j + 2);
            int   s3 = __shfl_sync(0xffffffffu, pk.x, j + 3);
            float m0 = __int_as_float(__shfl_sync(0xffffffffu, pk.y, j));
            float m1 = __int_as_float(__shfl_sync(0xffffffffu, pk.y, j + 1));
            float m2 = __int_as_float(__shfl_sync(0xffffffffu, pk.y, j + 2));
            float m3 = __int_as_float(__shfl_sync(0xffffffffu, pk.y, j + 3));
            float2 f0 = __half22float2(g_h[s0 * (D / 2) + lane]);
            float2 f1 = __half22float2(g_h[s1 * (D / 2) + lane]);
            float2 f2 = __half22float2(g_h[s2 * (D / 2) + lane]);
            float2 f3 = __half22float2(g_h[s3 * (D / 2) + lane]);
            acc.x = fmaf(m0, f0.x, acc.x); acc.y = fmaf(m0, f0.y, acc.y);
            acc.x = fmaf(m1, f1.x, acc.x); acc.y = fmaf(m1, f1.y, acc.y);
            acc.x = fmaf(m2, f2.x, acc.x); acc.y = fmaf(m2, f2.y, acc.y);
            acc.x = fmaf(m3, f3.x, acc.x); acc.y = fmaf(m3, f3.y, acc.y);
        }
        for (; j < n; j++) {
            int   sj = __shfl_sync(0xffffffffu, pk.x, j);
            float mj = __int_as_float(__shfl_sync(0xffffffffu, pk.y, j));
            float2 f = __half22float2(g_h[sj * (D / 2) + lane]);
            acc.x = fmaf(mj, f.x, acc.x);
            acc.y = fmaf(mj, f.y, acc.y);
        }
    }

    float2 bb = *(const float2*)&b[2 * lane];
    float2 o;
    o.x = fmaxf(fmaf(dd, acc.x, bb.x), 0.f);
    o.y = fmaxf(fmaf(dd, acc.y, bb.y), 0.f);
    *(float2*)&out[gw * D + 2 * lane] = o;
}

// ---------------------------------------------------------------------------
extern "C" void kernel_launch(void* const* d_in, const int* in_sizes, int n_in,
                              void* d_out, int out_size) {
    const float* x  = (const float*)d_in[0];
    const int*   ei = (const int*)d_in[1];     // [2, NE] row-major
    const float* ea = (const float*)d_in[2];
    const float* W  = (const float*)d_in[3];
    const float* b  = (const float*)d_in[4];
    float* out = (float*)d_out;

    const int* src = ei;
    const int* dst = ei + NE;

    k_deg<<<(NE + 255) / 256, 256>>>(dst, ea);
    k_offsets<<<NB, SCAN_B>>>();               // scan + rsqrt + pk64 reset
    k_fill<<<(NE + 255) / 256, 256>>>(src, dst, ea);
    k_gemm<<<(NN + GROWS - 1) / GROWS, 256>>>(x, W);   // + g_total reset
    k_aggr<<<(NN * 32 + 255) / 256, 256>>>(b, out);
}

// round 17
// speedup vs baseline: 1.1593x; 1.0798x over previous
#include <cuda_runtime.h>
#include <cuda_fp16.h>
#include <cstdint>

#define NN 100000
#define NE 1200000
#define D  64
#define SCAN_B 1024
#define NB ((NN + SCAN_B - 1) / SCAN_B)   // 98

#define GROWS 128
#define XST 72
#define GEMM_BLOCKS ((NN + GROWS - 1) / GROWS)     // 782
#define FILL_BLOCKS ((NE + 255) / 256)             // 4688

// Scratch (device globals — no allocation allowed; zero-initialized at load)
__device__ float              g_dis[NN];      // rsqrt(degree)
__device__ __half2            g_h[NN * D / 2];
__device__ unsigned long long g_pk64[NN];     // hi: count, lo: fixed-point wdeg
__device__ int                g_off[NN];      // segment start per node
__device__ int                g_cnt[NN];      // segment length per node
__device__ int                g_cur[NN];      // fill cursors
__device__ int                g_total;        // segment allocator
__device__ int2               g_pack[NE];     // {src, bits(dis[src]*ew)}

// ---------------------------------------------------------------------------
// one packed 64-bit atomic per edge: count + fixed-point weighted degree
__global__ void k_deg(const int* __restrict__ dst, const float* __restrict__ ew) {
    int e = blockIdx.x * blockDim.x + threadIdx.x;
    if (e < NE) {
        unsigned int q = __float2uint_rn(ew[e] * 16777216.0f);
        unsigned long long inc = (1ULL << 32) | (unsigned long long)q;
        atomicAdd(&g_pk64[dst[e]], inc);
    }
}

// ---------------------------------------------------------------------------
// Offsets in ONE kernel: block-local scan + one atomicAdd of the block total.
// Fuses dis = rsqrt(deg) and the g_pk64 reset.
__global__ __launch_bounds__(SCAN_B) void k_offsets() {
    __shared__ int wsum[32];
    __shared__ int s_base;
    const int i    = blockIdx.x * SCAN_B + threadIdx.x;
    const int lane = threadIdx.x & 31, w = threadIdx.x >> 5;

    unsigned long long p = (i < NN) ? g_pk64[i] : 0ULL;
    if (i < NN) g_pk64[i] = 0ULL;           // clean slate for next replay
    int v = (int)(p >> 32);
    int s = v;
    #pragma unroll
    for (int d = 1; d < 32; d <<= 1) {
        int t = __shfl_up_sync(0xffffffffu, s, d);
        if (lane >= d) s += t;
    }
    if (lane == 31) wsum[w] = s;
    __syncthreads();
    if (w == 0) {
        int t = wsum[lane];
        #pragma unroll
        for (int d = 1; d < 32; d <<= 1) {
            int u = __shfl_up_sync(0xffffffffu, t, d);
            if (lane >= d) t += u;
        }
        wsum[lane] = t;
    }
    __syncthreads();
    const int excl   = s + ((w > 0) ? wsum[w - 1] : 0) - v;  // block-local excl
    const int btotal = wsum[31];
    if (threadIdx.x == 0) s_base = atomicAdd(&g_total, btotal);
    __syncthreads();

    if (i < NN) {
        int o = s_base + excl;
        g_off[i] = o;
        g_cur[i] = o;
        g_cnt[i] = v;
        float deg = 1.0f + (float)(unsigned int)p * (1.0f / 16777216.0f);
        g_dis[i] = rsqrtf(deg);
    }
}

// ---------------------------------------------------------------------------
// FUSED fill + gemm: blocks [0, GEMM_BLOCKS) run the HMMA GEMM,
// blocks [GEMM_BLOCKS, GEMM_BLOCKS+FILL_BLOCKS) run the CSR fill.
// The two are data-independent; co-scheduling overlaps their latencies.
__global__ __launch_bounds__(256) void k_fill_gemm(
        const float* __restrict__ x, const float* __restrict__ W,
        const int* __restrict__ src, const int* __restrict__ dst,
        const float* __restrict__ ew) {
    if (blockIdx.x >= GEMM_BLOCKS) {
        // ---- fill branch ----
        int e = (blockIdx.x - GEMM_BLOCKS) * 256 + threadIdx.x;
        if (e >= NE) return;
        int s = src[e], d = dst[e];
        int pos = atomicAdd(&g_cur[d], 1);
        float m = g_dis[s] * ew[e];
        g_pack[pos] = make_int2(s, __float_as_int(m));
        return;
    }

    // ---- gemm branch ----
    if (blockIdx.x == 0 && threadIdx.x == 0) g_total = 0;  // reset for replay

    __shared__ __half Ws[D * XST];

    const int tid  = threadIdx.x;
    const int lane = tid & 31;
    const int wid  = tid >> 5;
    const int base = blockIdx.x * GROWS;

    for (int t = tid; t < D * D; t += 256) {
        int j = t >> 6, k = t & 63;
        Ws[j * XST + k] = __float2half_rn(W[t]);
    }
    __syncthreads();

    float acc[8][4];
    #pragma unroll
    for (int nb = 0; nb < 8; nb++)
        #pragma unroll
        for (int j = 0; j < 4; j++) acc[nb][j] = 0.f;

    const int gid = lane >> 2, tig = lane & 3;
    const int bn  = lane >> 2;            // B frag row within nb block
    const int bk0 = (lane & 3) << 1;      // B frag k offset
    const int r0  = base + wid * 16 + gid;
    const int r1  = r0 + 8;
    const bool v0 = r0 < NN, v1 = r1 < NN;
    const float* xr0 = &x[(size_t)(v0 ? r0 : 0) * D + 2 * tig];
    const float* xr1 = &x[(size_t)(v1 ? r1 : 0) * D + 2 * tig];

    // Prefetch ALL A-data: 16 independent 8B loads in flight.
    float2 f0v[8], f1v[8];                 // [kc*2 + half]
    {
        float2 z = make_float2(0.f, 0.f);
        #pragma unroll
        for (int kc = 0; kc < 4; kc++) {
            f0v[2 * kc]     = v0 ? *(const float2*)&xr0[16 * kc]     : z;
            f0v[2 * kc + 1] = v0 ? *(const float2*)&xr0[16 * kc + 8] : z;
            f1v[2 * kc]     = v1 ? *(const float2*)&xr1[16 * kc]     : z;
            f1v[2 * kc + 1] = v1 ? *(const float2*)&xr1[16 * kc + 8] : z;
        }
    }

    #pragma unroll
    for (int kc = 0; kc < 4; kc++) {
        __half2 ha0 = __floats2half2_rn(f0v[2 * kc].x,     f0v[2 * kc].y);
        __half2 ha1 = __floats2half2_rn(f1v[2 * kc].x,     f1v[2 * kc].y);
        __half2 ha2 = __floats2half2_rn(f0v[2 * kc + 1].x, f0v[2 * kc + 1].y);
        __half2 ha3 = __floats2half2_rn(f1v[2 * kc + 1].x, f1v[2 * kc + 1].y);
        uint32_t a0 = *(uint32_t*)&ha0, a1 = *(uint32_t*)&ha1;
        uint32_t a2 = *(uint32_t*)&ha2, a3 = *(uint32_t*)&ha3;

        #pragma unroll
        for (int nb = 0; nb < 8; nb++) {
            const __half* wp = &Ws[(nb * 8 + bn) * XST + kc * 16];
            uint32_t b0 = *(const uint32_t*)&wp[bk0];
            uint32_t b1 = *(const uint32_t*)&wp[bk0 + 8];
            asm volatile(
                "mma.sync.aligned.m16n8k16.row.col.f32.f16.f16.f32 "
                "{%0,%1,%2,%3}, {%4,%5,%6,%7}, {%8,%9}, {%0,%1,%2,%3};"
                : "+f"(acc[nb][0]), "+f"(acc[nb][1]),
                  "+f"(acc[nb][2]), "+f"(acc[nb][3])
                : "r"(a0), "r"(a1), "r"(a2), "r"(a3),
                  "r"(b0), "r"(b1));
        }
    }

    const int cc = tig << 1;
    #pragma unroll
    for (int nb = 0; nb < 8; nb++) {
        int c0 = nb * 8 + cc;
        if (v0) g_h[(r0 * D + c0) >> 1] = __floats2half2_rn(acc[nb][0], acc[nb][1]);
        if (v1) g_h[(r1 * D + c0) >> 1] = __floats2half2_rn(acc[nb][2], acc[nb][3]);
    }
}

// ---------------------------------------------------------------------------
// Aggregate (gather form): warp per dst node, unroll x4 for MLP.
// out[d] = relu( dis[d] * ( dis[d]*h[d] + sum_e m_e*h[src_e] ) + b )
__global__ __launch_bounds__(256) void k_aggr(const float* __restrict__ b,
                                              float* __restrict__ out) {
    int gw   = (blockIdx.x * 256 + threadIdx.x) >> 5;
    int lane = threadIdx.x & 31;
    if (gw >= NN) return;

    int off = g_off[gw];
    int end = off + g_cnt[gw];
    float dd = g_dis[gw];

    float2 hd = __half22float2(g_h[gw * (D / 2) + lane]);
    float2 acc = make_float2(dd * hd.x, dd * hd.y);

    for (int eb = off; eb < end; eb += 32) {
        int n = min(32, end - eb);
        int2 pk = make_int2(0, 0);
        if (lane < n) pk = g_pack[eb + lane];
        int j = 0;
        for (; j + 4 <= n; j += 4) {
            int   s0 = __shfl_sync(0xffffffffu, pk.x, j);
            int   s1 = __shfl_sync(0xffffffffu, pk.x, j + 1);
            int   s2 = __shfl_sync(0xffffffffu, pk.x, j + 2);
            int   s3 = __shfl_sync(0xffffffffu, pk.x, j + 3);
            float m0 = __int_as_float(__shfl_sync(0xffffffffu, pk.y, j));
            float m1 = __int_as_float(__shfl_sync(0xffffffffu, pk.y, j + 1));
            float m2 = __int_as_float(__shfl_sync(0xffffffffu, pk.y, j + 2));
            float m3 = __int_as_float(__shfl_sync(0xffffffffu, pk.y, j + 3));
            float2 f0 = __half22float2(g_h[s0 * (D / 2) + lane]);
            float2 f1 = __half22float2(g_h[s1 * (D / 2) + lane]);
            float2 f2 = __half22float2(g_h[s2 * (D / 2) + lane]);
            float2 f3 = __half22float2(g_h[s3 * (D / 2) + lane]);
            acc.x = fmaf(m0, f0.x, acc.x); acc.y = fmaf(m0, f0.y, acc.y);
            acc.x = fmaf(m1, f1.x, acc.x); acc.y = fmaf(m1, f1.y, acc.y);
            acc.x = fmaf(m2, f2.x, acc.x); acc.y = fmaf(m2, f2.y, acc.y);
            acc.x = fmaf(m3, f3.x, acc.x); acc.y = fmaf(m3, f3.y, acc.y);
        }
        for (; j < n; j++) {
            int   sj = __shfl_sync(0xffffffffu, pk.x, j);
            float mj = __int_as_float(__shfl_sync(0xffffffffu, pk.y, j));
            float2 f = __half22float2(g_h[sj * (D / 2) + lane]);
            acc.x = fmaf(mj, f.x, acc.x);
            acc.y = fmaf(mj, f.y, acc.y);
        }
    }

    float2 bb = *(const float2*)&b[2 * lane];
    float2 o;
    o.x = fmaxf(fmaf(dd, acc.x, bb.x), 0.f);
    o.y = fmaxf(fmaf(dd, acc.y, bb.y), 0.f);
    *(float2*)&out[gw * D + 2 * lane] = o;
}

// ---------------------------------------------------------------------------
extern "C" void kernel_launch(void* const* d_in, const int* in_sizes, int n_in,
                              void* d_out, int out_size) {
    const float* x  = (const float*)d_in[0];
    const int*   ei = (const int*)d_in[1];     // [2, NE] row-major
    const float* ea = (const float*)d_in[2];
    const float* W  = (const float*)d_in[3];
    const float* b  = (const float*)d_in[4];
    float* out = (float*)d_out;

    const int* src = ei;
    const int* dst = ei + NE;

    k_deg<<<(NE + 255) / 256, 256>>>(dst, ea);
    k_offsets<<<NB, SCAN_B>>>();               // scan + rsqrt + pk64 reset
    k_fill_gemm<<<GEMM_BLOCKS + FILL_BLOCKS, 256>>>(x, W, src, dst, ea);
    k_aggr<<<(NN * 32 + 255) / 256, 256>>>(b, out);
}